// round 12
// baseline (speedup 1.0000x reference)
#include <cuda_runtime.h>
#include <cstdint>

// ACT-LSTM persistent kernel, v7.
// vs v6: the t=0 fused pass (W_ih + W_hh, ~100 MB = the whole kernel since
// halting occurs at t=0) now streams weights through a cp.async double-
// buffered shared-memory pipeline. LDGSTS needs no destination registers,
// so ~112 KB is in flight per SM (vs ~3 KB/warp register-limited before),
// which is what Little's law requires to saturate HBM. Per-warp partial
// sums accumulate in registers across all 12 k-stages; ONE reduce per row
// at the end. Phases B/A and epilogue unchanged from v6 (correct, rarely
// hot).
//
// I=1024, H=2048, O=1024, 4H=8192, MAX_STEPS=20.

#define NBLOCK 148
#define NTHREAD 1024
#define WPB 32
#define HDIM 2048
#define IDIM 1024
#define ODIM 1024
#define G4 (4 * HDIM)            // 8192
#define MAX_STEPS 20
#define MAXROWS 56
#define KC 256                   // k-chunk (floats) per pipeline stage
#define N_IH_STAGES (IDIM / KC)  // 4
#define N_HH_STAGES (HDIM / KC)  // 8
#define N_STAGES (N_IH_STAGES + N_HH_STAGES)  // 12

// dynamic shared layout (floats):
//  sh_h[2048] | sh_c[2048] | sh_x[1024] | s_red[32] | s_hh[224] | buf0[14336] | buf1[14336]
#define SMEM_FLOATS (HDIM + HDIM + IDIM + 32 + 224 + 2 * MAXROWS * KC)
#define SMEM_BYTES (SMEM_FLOATS * 4)

// -------- device scratch --------
__device__ float g_gates[2][G4];
__device__ float g_gx_buf[G4];

// -------- manual grid barrier --------
__device__ unsigned g_bar_count = 0;
__device__ volatile unsigned g_bar_gen = 0;

__device__ __forceinline__ void grid_sync() {
    __syncthreads();
    if (threadIdx.x == 0) {
        __threadfence();
        unsigned gen = g_bar_gen;
        if (atomicAdd(&g_bar_count, 1u) == NBLOCK - 1) {
            g_bar_count = 0u;
            __threadfence();
            g_bar_gen = gen + 1u;
        } else {
            while (g_bar_gen == gen) { __nanosleep(32); }
            __threadfence();
        }
    }
    __syncthreads();
}

__device__ __forceinline__ float warp_reduce(float v) {
    #pragma unroll
    for (int off = 16; off; off >>= 1) v += __shfl_xor_sync(0xffffffffu, v, off);
    return v;
}

__device__ __forceinline__ float sigmoidf_(float x) {
    return 1.0f / (1.0f + __expf(-x));
}

__device__ __forceinline__ float dot4(float4 a, float4 b) {
    return a.x * b.x + a.y * b.y + a.z * b.z + a.w * b.w;
}

__device__ __forceinline__ void cp16(float* dst_s, const float* src_g) {
    uint32_t d = (uint32_t)__cvta_generic_to_shared(dst_s);
    asm volatile("cp.async.cg.shared.global [%0], [%1], 16;" :: "r"(d), "l"(src_g));
}
__device__ __forceinline__ void cp4(float* dst_s, const float* src_g) {
    uint32_t d = (uint32_t)__cvta_generic_to_shared(dst_s);
    asm volatile("cp.async.ca.shared.global [%0], [%1], 4;" :: "r"(d), "l"(src_g));
}

__global__ __launch_bounds__(NTHREAD, 1)
void act_lstm_kernel(const float* __restrict__ x,
                     const float* __restrict__ h0,
                     const float* __restrict__ c0,
                     const float* __restrict__ W_ih,
                     const float* __restrict__ W_hh,
                     const float* __restrict__ b_ih,
                     const float* __restrict__ b_hh,
                     const float* __restrict__ w_halt,
                     const float* __restrict__ b_halt,
                     const float* __restrict__ W_out,
                     const float* __restrict__ b_out,
                     float* __restrict__ out) {
    extern __shared__ float smem[];
    float* sh_h  = smem;                     // HDIM
    float* sh_c  = sh_h + HDIM;              // HDIM
    float* sh_x  = sh_c + HDIM;              // IDIM
    float* s_red = sh_x + IDIM;              // 32
    float* s_hh  = s_red + 32;               // 224
    float* buf0  = s_hh + 224;               // MAXROWS*KC
    float* buf1  = buf0 + MAXROWS * KC;      // MAXROWS*KC

    const int tid  = threadIdx.x;
    const int lane = tid & 31;
    const int warp = tid >> 5;
    const int bx   = blockIdx.x;

    // row chunk: 52 blocks get 56 rows, 96 get 55
    const int nrows = 55 + (bx < 52 ? 1 : 0);
    const int chunk = bx * 55 + (bx < 52 ? bx : 52);

    // ---- init block-local state ----
    for (int j = tid; j < HDIM; j += NTHREAD) {
        sh_h[j] = h0[j];
        sh_c[j] = c0[j];
    }
    sh_x[tid] = (tid < IDIM) ? x[tid] : 0.0f;   // NTHREAD==1024==IDIM anyway
    const float bh = b_halt[0];
    __syncthreads();

    // =========== fused t=0 pass: cp.async pipelined over 12 k-stages ==========
    // stage s<4:  W_ih[:,1+s*256 .. 1+(s+1)*256) -> buf       (4B cp, rows stride 1025)
    // stage s>=4: W_hh[:,(s-4)*256 .. (s-3)*256) -> buf       (16B cp)
    auto produce = [&](int s) {
        float* bufp = (s & 1) ? buf1 : buf0;
        if (s < N_IH_STAGES) {
            const int k0 = s * KC;
            const int total = nrows * KC;
            for (int idx = tid; idx < total; idx += NTHREAD) {
                const int row = idx >> 8;           // idx / KC
                const int off = idx & (KC - 1);
                cp4(bufp + row * KC + off,
                    W_ih + (size_t)(chunk + row) * (IDIM + 1) + 1 + k0 + off);
            }
        } else if (s < N_STAGES) {
            const int k0 = (s - N_IH_STAGES) * KC;
            const int total = nrows * (KC / 4);     // 16B units
            for (int idx = tid; idx < total; idx += NTHREAD) {
                const int row = idx >> 6;
                const int off = (idx & 63) << 2;
                cp16(bufp + row * KC + off,
                     W_hh + (size_t)(chunk + row) * HDIM + k0 + off);
            }
        }
        asm volatile("cp.async.commit_group;");
    };

    const int lr0 = warp;
    const int lr1 = warp + 32;
    const bool has1 = (lr1 < nrows);
    float aih0 = 0.f, aih1 = 0.f, ahh0 = 0.f, ahh1 = 0.f;

    produce(0);
    produce(1);
    for (int s = 0; s < N_STAGES; ++s) {
        asm volatile("cp.async.wait_group 1;");     // stage s complete
        __syncthreads();
        const float* bufp = (s & 1) ? buf1 : buf0;
        if (s < N_IH_STAGES) {
            const float4* xs = (const float4*)(sh_x + s * KC);
            float4 x0 = xs[lane], x1 = xs[lane + 32];
            const float4* w = (const float4*)(bufp + lr0 * KC);
            aih0 += dot4(w[lane], x0) + dot4(w[lane + 32], x1);
            if (has1) {
                const float4* w1 = (const float4*)(bufp + lr1 * KC);
                aih1 += dot4(w1[lane], x0) + dot4(w1[lane + 32], x1);
            }
        } else {
            const float4* hs = (const float4*)(sh_h + (s - N_IH_STAGES) * KC);
            float4 h0v = hs[lane], h1v = hs[lane + 32];
            const float4* w = (const float4*)(bufp + lr0 * KC);
            ahh0 += dot4(w[lane], h0v) + dot4(w[lane + 32], h1v);
            if (has1) {
                const float4* w1 = (const float4*)(bufp + lr1 * KC);
                ahh1 += dot4(w1[lane], h0v) + dot4(w1[lane + 32], h1v);
            }
        }
        __syncthreads();
        produce(s + 2);                             // empty commit past the end
    }

    // one reduce per row for the whole pass; lane0 writes gates directly
    aih0 = warp_reduce(aih0); ahh0 = warp_reduce(ahh0);
    aih1 = warp_reduce(aih1); ahh1 = warp_reduce(ahh1);
    if (lane == 0) {
        const int r = chunk + lr0;
        float base = aih0 + b_ih[r] + b_hh[r];
        g_gx_buf[r] = base;
        g_gates[0][r] = base + __ldg(W_ih + (size_t)r * (IDIM + 1)) + ahh0;
        if (has1) {
            const int r1 = chunk + lr1;
            float base1 = aih1 + b_ih[r1] + b_hh[r1];
            g_gx_buf[r1] = base1;
            g_gates[0][r1] = base1 + __ldg(W_ih + (size_t)r1 * (IDIM + 1)) + ahh1;
        }
    }
    grid_sync();

    // ---- adaptive loop: ONE grid barrier per step ----
    float cum = 0.0f;
    int   halted_t = MAX_STEPS - 1;
    int   buf = 0;
    const int nunits = nrows * 4;

    for (int t = 0; t < MAX_STEPS; ++t) {
        // phase B: activations + halt (redundant per block)
        const float* gt = g_gates[buf];
        float part = 0.0f;
        #pragma unroll
        for (int j = tid; j < HDIM; j += NTHREAD) {
            float gi = gt[j];
            float gf = gt[HDIM + j];
            float gg = gt[2 * HDIM + j];
            float go = gt[3 * HDIM + j];
            float cn = sigmoidf_(gf) * sh_c[j] + sigmoidf_(gi) * tanhf(gg);
            float hn = sigmoidf_(go) * tanhf(cn);
            sh_c[j] = cn;
            sh_h[j] = hn;
            part += w_halt[j] * hn;
        }
        part = warp_reduce(part);
        if (lane == 0) s_red[warp] = part;
        __syncthreads();
        float dot = 0.0f;
        #pragma unroll
        for (int w2 = 0; w2 < WPB; ++w2) dot += s_red[w2];
        float p = sigmoidf_(dot + bh);
        cum += p;
        if (cum >= 0.99f || t == MAX_STEPS - 1) { halted_t = t; break; }

        // phase A for step t+1 (cold path): gates = gx + W_hh @ h
        buf ^= 1;
        float* gn = g_gates[buf];
        for (int u = warp; u < nunits; u += WPB) {
            const int r = chunk + (u >> 2);
            const int q = u & 3;
            const float4* wh = (const float4*)(W_hh + (size_t)r * HDIM) + (q << 7) + lane;
            const float4* hv = (const float4*)sh_h + (q << 7) + lane;
            float4 w0 = __ldg(wh);
            float4 w1 = __ldg(wh + 32);
            float4 w2 = __ldg(wh + 64);
            float4 w3 = __ldg(wh + 96);
            float4 hA = hv[0], hB = hv[32], hC = hv[64], hD = hv[96];
            float hh = (dot4(w0, hA) + dot4(w1, hB)) + (dot4(w2, hC) + dot4(w3, hD));
            hh = warp_reduce(hh);
            if (lane == 0) s_hh[u] = hh;
        }
        __syncthreads();
        if (tid < nrows) {
            const int r = chunk + tid;
            gn[r] = g_gx_buf[r]
                  + (s_hh[4 * tid] + s_hh[4 * tid + 1])
                  + (s_hh[4 * tid + 2] + s_hh[4 * tid + 3]);
        }
        grid_sync();
    }

    // ---- epilogue (barrier-free): out = W_out @ h + b_out ----
    __syncthreads();
    {
        const int orows  = 6 + (bx < 136 ? 1 : 0);
        const int ostart = bx * 6 + (bx < 136 ? bx : 136);
        const int ounits = orows * 4;
        if (warp < ounits) {
            const int row = ostart + (warp >> 2);
            const int q   = warp & 3;
            const float4* wr = (const float4*)(W_out + (size_t)row * HDIM) + (q << 7) + lane;
            const float4* hv = (const float4*)sh_h + (q << 7) + lane;
            float4 w0 = __ldg(wr);
            float4 w1 = __ldg(wr + 32);
            float4 w2 = __ldg(wr + 64);
            float4 w3 = __ldg(wr + 96);
            float4 hA = hv[0], hB = hv[32], hC = hv[64], hD = hv[96];
            float a = (dot4(w0, hA) + dot4(w1, hB)) + (dot4(w2, hC) + dot4(w3, hD));
            a = warp_reduce(a);
            if (lane == 0) s_hh[warp] = a;
        }
        __syncthreads();
        if (tid < orows) {
            const int row = ostart + tid;
            out[row] = (s_hh[4 * tid] + s_hh[4 * tid + 1])
                     + (s_hh[4 * tid + 2] + s_hh[4 * tid + 3]) + b_out[row];
        }
    }

    if (bx == 0) {
        for (int j = tid; j < HDIM; j += NTHREAD) {
            out[ODIM + j]        = sh_h[j];
            out[ODIM + HDIM + j] = sh_c[j];
        }
        if (tid == 0) out[ODIM + 2 * HDIM] = (float)halted_t;
    }
}

extern "C" void kernel_launch(void* const* d_in, const int* in_sizes, int n_in,
                              void* d_out, int out_size) {
    (void)in_sizes; (void)n_in; (void)out_size;
    const float* x      = (const float*)d_in[0];
    const float* h0     = (const float*)d_in[1];
    const float* c0     = (const float*)d_in[2];
    const float* W_ih   = (const float*)d_in[3];
    const float* W_hh   = (const float*)d_in[4];
    const float* b_ih   = (const float*)d_in[5];
    const float* b_hh   = (const float*)d_in[6];
    const float* w_halt = (const float*)d_in[7];
    const float* b_halt = (const float*)d_in[8];
    const float* W_out  = (const float*)d_in[9];
    const float* b_out  = (const float*)d_in[10];
    float* out = (float*)d_out;

    cudaFuncSetAttribute(act_lstm_kernel,
                         cudaFuncAttributeMaxDynamicSharedMemorySize, SMEM_BYTES);
    act_lstm_kernel<<<NBLOCK, NTHREAD, SMEM_BYTES>>>(x, h0, c0, W_ih, W_hh,
                                                     b_ih, b_hh, w_halt, b_halt,
                                                     W_out, b_out, out);
}